// round 10
// baseline (speedup 1.0000x reference)
#include <cuda_runtime.h>
#include <cstdint>

#define GRID_C 148

__device__ float G1d[2097152]; // [8192][256] = 1 - h1^2
__device__ float G2d[2097152]; // [8192][256] = 1 - h2^2
__device__ float W2P[65536];   // frag-permuted tf32 W2: [c][lt][ks][lane][2] (L2-resident B)
__device__ float W1P[16384];   // frag-permuted tf32 W1: [jt][ksg][lane][2]
__device__ float W3P[16384];   // frag-permuted tf32 W3^T (A-side): [mt][ks][lane][4]

typedef unsigned long long u64;
__device__ __forceinline__ float rnaf(float f){
    uint32_t o; asm("cvt.rna.tf32.f32 %0, %1;" : "=r"(o) : "f"(f)); return __uint_as_float(o);
}
__device__ __forceinline__ u64 pk2(float s){ u64 r; asm("mov.b64 %0,{%1,%1};" : "=l"(r) : "f"(s)); return r; }
__device__ __forceinline__ u64 fma2(u64 a, u64 b, u64 c){ u64 d; asm("fma.rn.f32x2 %0,%1,%2,%3;" : "=l"(d) : "l"(a), "l"(b), "l"(c)); return d; }
__device__ __forceinline__ void mma8(float* c, const uint32_t* a, const uint32_t* b){
    asm volatile("mma.sync.aligned.m16n8k8.row.col.f32.tf32.tf32.f32 "
        "{%0,%1,%2,%3},{%4,%5,%6,%7},{%8,%9},{%0,%1,%2,%3};"
        : "+f"(c[0]), "+f"(c[1]), "+f"(c[2]), "+f"(c[3])
        : "r"(a[0]), "r"(a[1]), "r"(a[2]), "r"(a[3]), "r"(b[0]), "r"(b[1]));
}
#define CPA(dst, src) asm volatile("cp.async.cg.shared.global [%0],[%1],16;" :: "r"(dst), "l"(src) : "memory")
__device__ __forceinline__ uint32_t su32(const void* p){
    uint32_t a; asm("{.reg .u64 t; cvta.to.shared.u64 t,%1; cvt.u32.u64 %0,t;}" : "=r"(a) : "l"(p)); return a;
}
#define WGBAR(id) asm volatile("bar.sync %0, 256;" :: "r"(id) : "memory")

// ---------------- prep: fragment-permuted tf32 weight images ----------------
__global__ void prep(const float* __restrict__ W1, const float* __restrict__ W2,
                     const float* __restrict__ W3){
    int i = blockIdx.x * blockDim.x + threadIdx.x, stride = gridDim.x * blockDim.x;
    for (int idx = i; idx < 65536; idx += stride){
        int w = idx & 1, lane = (idx >> 1) & 31, ks = (idx >> 6) & 31, lt = (idx >> 11) & 3, c = idx >> 13;
        int l = c * 32 + lt * 8 + (lane >> 2), k = ks * 8 + (lane & 3) + 4 * w;
        W2P[idx] = rnaf(W2[l * 256 + k]);
    }
    for (int idx = i; idx < 16384; idx += stride){
        int w = idx & 1, lane = (idx >> 1) & 31, ksg = (idx >> 6) & 31, jt = idx >> 11;
        int j = jt * 8 + (lane >> 2), l = ksg * 8 + (lane & 3) + 4 * w;
        W1P[idx] = rnaf(W1[j * 256 + l]);
    }
    for (int idx = i; idx < 16384; idx += stride){
        int w = idx & 3, lane = (idx >> 2) & 31, ks = (idx >> 7) & 31, mt = idx >> 12;
        int m = mt * 16 + (lane >> 2) + 8 * (w & 1);
        int k = ks * 8 + (lane & 3) + 4 * (w >> 1);
        W3P[idx] = rnaf(W3[k * 64 + m]);
    }
}

// ---------------- fwd: exact fp32 g1/g2 for all batches ----------------
__global__ void __launch_bounds__(256, 1) fwd(const float* __restrict__ x, const float* __restrict__ W1,
                                              const float* __restrict__ b1, const float* __restrict__ W2,
                                              const float* __restrict__ b2){
    extern __shared__ float fs[];
    float* xs  = fs;             // [64 j][66]
    float* h1t = fs + 64 * 66;   // [256 l][66]
    const int t = threadIdx.x;
    const int b0 = blockIdx.x * 64;
    for (int r = 0; r < 16; r++){
        int idx = r * 256 + t, b = idx >> 6, j = idx & 63;
        xs[j * 66 + b] = x[(size_t)(b0 + b) * 64 + j];
    }
    __syncthreads();
    u64 acc[32];
    #pragma unroll
    for (int q = 0; q < 32; q++) acc[q] = 0ull;
    for (int j = 0; j < 64; j++){
        u64 wp = pk2(W1[j * 256 + t]);
        const u64* xr = (const u64*)(xs + j * 66);
        #pragma unroll
        for (int q = 0; q < 32; q++) acc[q] = fma2(xr[q], wp, acc[q]);
    }
    float bb = b1[t];
    #pragma unroll
    for (int q = 0; q < 32; q++){
        float2 f; asm("mov.b64 {%0,%1},%2;" : "=f"(f.x), "=f"(f.y) : "l"(acc[q]));
        float ha = tanhf(f.x + bb), hb = tanhf(f.y + bb);
        h1t[t * 66 + 2*q] = ha; h1t[t * 66 + 2*q + 1] = hb;
        G1d[(size_t)(b0 + 2*q) * 256 + t]     = 1.f - ha * ha;
        G1d[(size_t)(b0 + 2*q + 1) * 256 + t] = 1.f - hb * hb;
    }
    __syncthreads();
    #pragma unroll
    for (int q = 0; q < 32; q++) acc[q] = 0ull;
    for (int l = 0; l < 256; l++){
        u64 wp = pk2(W2[l * 256 + t]);
        const u64* hr = (const u64*)(h1t + l * 66);
        #pragma unroll
        for (int q = 0; q < 32; q++) acc[q] = fma2(hr[q], wp, acc[q]);
    }
    bb = b2[t];
    #pragma unroll
    for (int q = 0; q < 32; q++){
        float2 f; asm("mov.b64 {%0,%1},%2;" : "=f"(f.x), "=f"(f.y) : "l"(acc[q]));
        float ha = tanhf(f.x + bb), hb = tanhf(f.y + bb);
        G2d[(size_t)(b0 + 2*q) * 256 + t]     = 1.f - ha * ha;
        G2d[(size_t)(b0 + 2*q + 1) * 256 + t] = 1.f - hb * hb;
    }
}

// ---------------- jmain: 512 thr, 2 batches/CTA, m64n32 strips, B via LDG ----------------
// smem floats: W3s 16384 | C1P 2x16384 | g2s 2x256   = 198,656 B
#define SMF (16384 + 32768 + 512)

__global__ void __launch_bounds__(512, 1) jmain(float* __restrict__ out){
    extern __shared__ float s[];
    float* W3s = s;                 // 16384
    float* C1P = s + 16384;         // 2 x 16384 (full A2 image per batch)
    float* g2s = C1P + 32768;       // 2 x 256

    const int t = threadIdx.x, lane = t & 31, wid = t >> 5;
    const int wg = wid >> 3, w8 = wid & 7;
    const int g = lane >> 2, tg = lane & 3;
    const int t2 = t & 255;

    float* C1w = C1P + wg * 16384;
    float* g2w = g2s + wg * 256;
    const uint32_t w3sb = su32(W3s);

    // resident W3P (A operand), loaded once
    #pragma unroll
    for (int i = 0; i < 8; i++){
        int u = t + i * 512;
        CPA(w3sb + (uint32_t)u * 16, (const char*)W3P + u * 16);
    }
    asm volatile("cp.async.commit_group;\ncp.async.wait_group 0;" ::: "memory");
    __syncthreads();

    const float4* Ap  = (const float4*)W3s + lane;
    const float4* A2b = (const float4*)C1w;
    const float2* Bp2 = (const float2*)W2P + (size_t)(w8 * 4) * 1024 + lane;
    const float2* B2p = (const float2*)W1P + (size_t)w8 * 1024 + lane;
    const int idxA = tg * 8 + g;

    for (int p = blockIdx.x; p < 4096; p += GRID_C){
        const int b = 2 * p + wg;
        g2w[t2] = G2d[(size_t)b * 256 + t2];
        WGBAR(1 + wg);   // g2 visible; all wg warps past prior GEMM2 (C1P safe to overwrite)

        // ---- GEMM1: warp strip l in [32*w8, 32*w8+32), full K=256 ----
        float C1r[4][4][4];   // [f (n8 frag)][mt][q]
        #pragma unroll
        for (int f = 0; f < 4; f++)
            #pragma unroll
            for (int mt = 0; mt < 4; mt++)
                #pragma unroll
                for (int q = 0; q < 4; q++) C1r[f][mt][q] = 0.f;

        #pragma unroll 4
        for (int ks = 0; ks < 32; ks++){
            const float ga = g2w[ks * 8 + tg], gb = g2w[ks * 8 + tg + 4];
            float2 Bs[4];
            #pragma unroll
            for (int f = 0; f < 4; f++){
                float2 Br = Bp2[(f * 32 + ks) * 32];
                Bs[f].x = rnaf(Br.x * ga); Bs[f].y = rnaf(Br.y * gb);
            }
            #pragma unroll
            for (int mt = 0; mt < 4; mt++){
                float4 A = Ap[(mt * 32 + ks) * 32];
                #pragma unroll
                for (int f = 0; f < 4; f++)
                    mma8(C1r[f][mt], (const uint32_t*)&A, (const uint32_t*)&Bs[f]);
            }
        }

        // ---- park: scale by g1, write frag-permuted A2 image [mt][ss][tg*8+g][w] ----
        {
            const float* g1b = G1d + (size_t)b * 256 + 32 * w8;
            #pragma unroll
            for (int f = 0; f < 4; f++){
                const float g1v0 = __ldg(g1b + 8 * f + 2 * tg);
                const float g1v1 = __ldg(g1b + 8 * f + 2 * tg + 1);
                const int ss = 4 * w8 + f;
                #pragma unroll
                for (int q = 0; q < 4; q++){
                    const int par = q & 1;
                    const int l7 = 2 * tg + par;
                    const int tgp = l7 & 3, kh = l7 >> 2;
                    const int wq = (q >> 1) + 2 * kh;
                    const float gv = par ? g1v1 : g1v0;
                    #pragma unroll
                    for (int mt = 0; mt < 4; mt++)
                        C1w[((mt * 32 + ss) * 32 + tgp * 8 + g) * 4 + wq] = rnaf(C1r[f][mt][q] * gv);
                }
            }
        }
        WGBAR(1 + wg);

        // ---- GEMM2: J[m64, j8-strip] = A2 x W1, full K=256 ----
        float J[4][4];
        #pragma unroll
        for (int mt = 0; mt < 4; mt++)
            #pragma unroll
            for (int q = 0; q < 4; q++) J[mt][q] = 0.f;

        #pragma unroll 4
        for (int ss = 0; ss < 32; ss++){
            float2 B = B2p[ss * 32];
            #pragma unroll
            for (int mt = 0; mt < 4; mt++){
                float4 A = A2b[(mt * 32 + ss) * 32 + idxA];
                mma8(J[mt], (const uint32_t*)&A, (const uint32_t*)&B);
            }
        }

        // ---- epilogue: J -> out[b] ----
        {
            float* ob = out + (size_t)b * 4096;
            const int cc = w8 * 8 + 2 * tg;
            #pragma unroll
            for (int mt = 0; mt < 4; mt++){
                const int r0 = mt * 16 + g;
                *(float2*)(ob + (size_t)r0 * 64 + cc)       = make_float2(J[mt][0], J[mt][1]);
                *(float2*)(ob + (size_t)(r0 + 8) * 64 + cc) = make_float2(J[mt][2], J[mt][3]);
            }
        }
    }
}

extern "C" void kernel_launch(void* const* d_in, const int* in_sizes, int n_in,
                              void* d_out, int out_size)
{
    const float* x  = (const float*)d_in[0];
    const float* W1 = (const float*)d_in[1];
    const float* b1 = (const float*)d_in[2];
    const float* W2 = (const float*)d_in[3];
    const float* b2 = (const float*)d_in[4];
    const float* W3 = (const float*)d_in[5];
    float* out = (float*)d_out;

    cudaFuncSetAttribute(fwd,   cudaFuncAttributeMaxDynamicSharedMemorySize, (64*66 + 256*66) * 4);
    cudaFuncSetAttribute(jmain, cudaFuncAttributeMaxDynamicSharedMemorySize, SMF * 4);

    prep<<<64, 256>>>(W1, W2, W3);
    fwd<<<128, 256, (64*66 + 256*66) * 4>>>(x, W1, b1, W2, b2);
    jmain<<<GRID_C, 512, SMF * 4>>>(out);
}